// round 2
// baseline (speedup 1.0000x reference)
#include <cuda_runtime.h>
#include <math.h>

#define BB 4
#define SS 2048
#define HH 16
#define DD 128
#define DH 64    // effective qk dim (first half, duplicated in reference)
#define BM 64
#define BN 64

// Scratch (no allocations allowed): head-major preprocessed tensors.
__device__ float g_Qp[BB*HH*SS*DH];   // 33.5 MB
__device__ float g_Kp[BB*HH*SS*DH];   // 33.5 MB
__device__ float g_Vt[BB*HH*SS*DD];   // 67 MB

// Q'[b,h,s,i] = q[b,s,h,i] * fc(s,i); same for K'.
// fc(s,i) = 2 * (s * theta^(-i/64)); the *2 is exact (power of two),
// inv computed in double then rounded -> matches fp32 reference to ~1ulp.
__global__ void prep_qk(const float* __restrict__ q, const float* __restrict__ k) {
    int tid = blockIdx.x * blockDim.x + threadIdx.x;
    if (tid >= BB*HH*SS*DH) return;
    int i = tid & 63;
    int s = (tid >> 6) & 2047;
    int h = (tid >> 17) & 15;
    int b = tid >> 21;
    float inv = (float)exp(-(double)i * (9.210340371976184 / 64.0)); // ln(1e4)/64
    float fc = 2.0f * ((float)s * inv);
    int gin = ((b*SS + s)*HH + h)*DD + i;
    g_Qp[tid] = q[gin] * fc;
    g_Kp[tid] = k[gin] * fc;
}

__global__ void prep_v(const float* __restrict__ v) {
    int tid = blockIdx.x * blockDim.x + threadIdx.x;
    if (tid >= BB*HH*SS*DD) return;
    int d = tid & 127;
    int s = (tid >> 7) & 2047;
    int h = (tid >> 18) & 15;
    int b = tid >> 22;
    g_Vt[tid] = v[((b*SS + s)*HH + h)*DD + d];
}

// Flash-attention tile kernel: BM=64 queries x full key loop (BN=64 tiles).
// 256 threads: GEMM1 (64x64, 4x4 micro), GEMM2 (64x128, 4x8 micro).
__global__ __launch_bounds__(256, 2)
void attn_kernel(float* __restrict__ out) {
    extern __shared__ float sm[];
    float* Qs  = sm;                 // 64 x 65
    float* Ks  = Qs + BM*65;         // 64 x 65
    float* Ps  = Ks + BN*65;         // 64 x 65
    float* Vs  = Ps + BM*65;         // 64 x 128 (16B-aligned: 12480 floats before)
    float* mrow = Vs + BN*DD;        // 64
    float* lrow = mrow + BM;         // 64
    float* facr = lrow + BM;         // 64
    float* mnew = facr + BM;         // 64

    const int qt = blockIdx.x, h = blockIdx.y, b = blockIdx.z;
    const int tid = threadIdx.x;
    const int ti = tid >> 4;         // 0..15
    const int tj = tid & 15;         // 0..15

    const float* Qg  = g_Qp + (((b*HH + h)*SS) + qt*BM)*DH;
    const float* Kg0 = g_Kp + ((b*HH + h)*SS)*DH;
    const float* Vg0 = g_Vt + ((b*HH + h)*SS)*DD;

    // Load Q tile once
    for (int idx = tid; idx < BM*DH; idx += 256) {
        int r = idx >> 6, c = idx & 63;
        Qs[r*65 + c] = Qg[idx];
    }
    if (tid < BM) { mrow[tid] = -INFINITY; lrow[tid] = 0.0f; }

    float o[4][8];
    #pragma unroll
    for (int rx = 0; rx < 4; rx++)
        #pragma unroll
        for (int c = 0; c < 8; c++) o[rx][c] = 0.0f;

    for (int kt = 0; kt < SS/BN; ++kt) {
        __syncthreads();   // prev iteration fully done with Ks/Vs/Ps; Qs ready on iter 0

        // Load K' and V tiles
        const float* Kg = Kg0 + kt*BN*DH;
        for (int idx = tid; idx < BN*DH; idx += 256) {
            int r = idx >> 6, c = idx & 63;
            Ks[r*65 + c] = Kg[idx];
        }
        {
            const float4* Vg = (const float4*)(Vg0 + kt*BN*DD);
            float4* Vs4 = (float4*)Vs;
            for (int idx = tid; idx < BN*DD/4; idx += 256) Vs4[idx] = Vg[idx];
        }
        __syncthreads();

        // GEMM1: S = Q' K'^T  (scaled by 1/64)
        float acc[4][4];
        #pragma unroll
        for (int rx = 0; rx < 4; rx++)
            #pragma unroll
            for (int cx = 0; cx < 4; cx++) acc[rx][cx] = 0.0f;

        #pragma unroll 16
        for (int kk = 0; kk < DH; ++kk) {
            float a[4], bb[4];
            #pragma unroll
            for (int x = 0; x < 4; x++) a[x]  = Qs[(ti*4 + x)*65 + kk];
            #pragma unroll
            for (int x = 0; x < 4; x++) bb[x] = Ks[(tj*4 + x)*65 + kk];
            #pragma unroll
            for (int rx = 0; rx < 4; rx++)
                #pragma unroll
                for (int cx = 0; cx < 4; cx++)
                    acc[rx][cx] += a[rx] * bb[cx];
        }
        const float sc = 1.0f / 64.0f;   // exact power-of-two scale (== 2/128)
        #pragma unroll
        for (int rx = 0; rx < 4; rx++)
            #pragma unroll
            for (int cx = 0; cx < 4; cx++)
                Ps[(ti*4 + rx)*65 + tj*4 + cx] = acc[rx][cx] * sc;
        __syncthreads();

        // Row max + online-softmax factors
        if (tid < BM) {
            float mx = -INFINITY;
            for (int j = 0; j < BN; j++) mx = fmaxf(mx, Ps[tid*65 + j]);
            float mo = mrow[tid];
            float mn = fmaxf(mo, mx);
            mrow[tid] = mn;
            mnew[tid] = mn;
            facr[tid] = expf(mo - mn);   // expf(-inf)=0 on first tile
        }
        __syncthreads();

        // P = exp(S - m_new) in place; rescale O by factor
        #pragma unroll
        for (int rx = 0; rx < 4; rx++) {
            int r = ti*4 + rx;
            float mn = mnew[r];
            #pragma unroll
            for (int cx = 0; cx < 4; cx++) {
                int idx = r*65 + tj*4 + cx;
                Ps[idx] = expf(Ps[idx] - mn);
            }
            float f = facr[r];
            #pragma unroll
            for (int c = 0; c < 8; c++) o[rx][c] *= f;
        }
        __syncthreads();

        // l update (reads only; overlaps with GEMM2 reads)
        if (tid < BM) {
            float sum = 0.0f;
            for (int j = 0; j < BN; j++) sum += Ps[tid*65 + j];
            lrow[tid] = lrow[tid]*facr[tid] + sum;
        }

        // GEMM2: O += P V
        #pragma unroll 8
        for (int kk = 0; kk < BN; ++kk) {
            float a[4];
            #pragma unroll
            for (int rx = 0; rx < 4; rx++) a[rx] = Ps[(ti*4 + rx)*65 + kk];
            float4 v0 = *(const float4*)&Vs[kk*DD + tj*8];
            float4 v1 = *(const float4*)&Vs[kk*DD + tj*8 + 4];
            #pragma unroll
            for (int rx = 0; rx < 4; rx++) {
                o[rx][0] += a[rx]*v0.x;  o[rx][1] += a[rx]*v0.y;
                o[rx][2] += a[rx]*v0.z;  o[rx][3] += a[rx]*v0.w;
                o[rx][4] += a[rx]*v1.x;  o[rx][5] += a[rx]*v1.y;
                o[rx][6] += a[rx]*v1.z;  o[rx][7] += a[rx]*v1.w;
            }
        }
    }
    __syncthreads();

    // Normalize and write: out[(b*S+s)*H*D + h*D + d]
    #pragma unroll
    for (int rx = 0; rx < 4; rx++) {
        int srow = qt*BM + ti*4 + rx;
        float inv_l = 1.0f / lrow[ti*4 + rx];
        float* op = out + (((size_t)b*SS + srow)*HH + h)*DD + tj*8;
        float4 w0, w1;
        w0.x = o[rx][0]*inv_l; w0.y = o[rx][1]*inv_l;
        w0.z = o[rx][2]*inv_l; w0.w = o[rx][3]*inv_l;
        w1.x = o[rx][4]*inv_l; w1.y = o[rx][5]*inv_l;
        w1.z = o[rx][6]*inv_l; w1.w = o[rx][7]*inv_l;
        *(float4*)op = w0;
        *(float4*)(op + 4) = w1;
    }
}

extern "C" void kernel_launch(void* const* d_in, const int* in_sizes, int n_in,
                              void* d_out, int out_size) {
    const float* q = (const float*)d_in[0];
    const float* k = (const float*)d_in[1];
    const float* v = (const float*)d_in[2];
    float* out = (float*)d_out;

    const int smem = (3*BM*65 + BN*DD + 4*BM) * (int)sizeof(float);  // 83712 B
    cudaFuncSetAttribute(attn_kernel, cudaFuncAttributeMaxDynamicSharedMemorySize, smem);

    prep_qk<<<(BB*HH*SS*DH + 255)/256, 256>>>(q, k);
    prep_v<<<(BB*HH*SS*DD + 255)/256, 256>>>(v);

    dim3 grid(SS/BM, HH, BB);
    attn_kernel<<<grid, 256, smem>>>(out);
}

// round 3
// speedup vs baseline: 1.1452x; 1.1452x over previous
#include <cuda_runtime.h>
#include <math.h>

#define BB 4
#define SS 2048
#define HH 16
#define DD 128
#define DH 64    // effective qk dim (first half, duplicated in reference)
#define BM 64
#define BN 64
#define PSTR 66

// Scratch (no allocations allowed): k-major preprocessed Q', K'.
__device__ float g_Qp[BB*HH*DH*SS];   // [b,h,kdim,s]  33.5 MB
__device__ float g_Kp[BB*HH*DH*SS];   // [b,h,kdim,s]  33.5 MB
__device__ float g_inv[DH];

// ---------------- packed f32x2 helpers (sm_103a) ----------------
__device__ __forceinline__ unsigned long long bcast2(float x) {
    unsigned long long r;
    asm("mov.b64 %0, {%1, %1};" : "=l"(r) : "f"(x));
    return r;
}
__device__ __forceinline__ void ffma2(unsigned long long& d,
                                      unsigned long long a,
                                      unsigned long long b) {
    asm("fma.rn.f32x2 %0, %1, %2, %3;" : "=l"(d) : "l"(a), "l"(b), "l"(d));
}
__device__ __forceinline__ unsigned long long mul2(unsigned long long a,
                                                   unsigned long long b) {
    unsigned long long d;
    asm("mul.rn.f32x2 %0, %1, %2;" : "=l"(d) : "l"(a), "l"(b));
    return d;
}
__device__ __forceinline__ void unpack2(unsigned long long v, float& lo, float& hi) {
    asm("mov.b64 {%0, %1}, %2;" : "=f"(lo), "=f"(hi) : "l"(v));
}

// ---------------- prep ----------------
// inv[i] = theta^(-i/64) computed in double once (matches fp32 ref to ~1ulp)
__global__ void init_inv() {
    int i = threadIdx.x;
    g_inv[i] = (float)exp(-(double)i * (9.210340371976184 / 64.0)); // ln(1e4)/64
}

// Tiled transpose: q,k [b,s,h,128] (first 64 dims) * fc -> [b,h,64,s]
__global__ void prep_qk(const float* __restrict__ q, const float* __restrict__ k) {
    __shared__ float qs[64*65];
    __shared__ float ks[64*65];
    const int st = blockIdx.x, h = blockIdx.y, b = blockIdx.z;
    const int tid = threadIdx.x;
    for (int idx = tid; idx < 64*64; idx += 256) {
        int sl = idx >> 6, i = idx & 63;
        int s = st*64 + sl;
        float fc = 2.0f * ((float)s * g_inv[i]);
        size_t gin = ((size_t)(b*SS + s)*HH + h)*DD + i;
        qs[i*65 + sl] = q[gin] * fc;
        ks[i*65 + sl] = k[gin] * fc;
    }
    __syncthreads();
    float* Qo = g_Qp + (size_t)((b*HH + h)*DH)*SS + st*64;
    float* Ko = g_Kp + (size_t)((b*HH + h)*DH)*SS + st*64;
    for (int idx = tid; idx < 64*64; idx += 256) {
        int i = idx >> 6, sl = idx & 63;
        Qo[(size_t)i*SS + sl] = qs[i*65 + sl];
        Ko[(size_t)i*SS + sl] = ks[i*65 + sl];
    }
}

// ---------------- flash attention, FFMA2 micro-kernels ----------------
__global__ __launch_bounds__(256, 2)
void attn_kernel(const float* __restrict__ v, float* __restrict__ out) {
    extern __shared__ float sm[];
    float* QsT = sm;               // [64 kdim][64 m]
    float* KsT = QsT + 4096;       // [64 kdim][64 n]
    float* Vs  = KsT + 4096;       // [64 n][128 d]
    float* Ps  = Vs + 8192;        // [64 m][66]

    const int qt = blockIdx.x, h = blockIdx.y, b = blockIdx.z;
    const int tid = threadIdx.x;
    const int ti = tid >> 4;       // 0..15 -> row group
    const int tj = tid & 15;       // 0..15 -> col group

    const float* Qg  = g_Qp + (size_t)((b*HH + h)*DH)*SS + qt*BM;
    const float* Kg0 = g_Kp + (size_t)((b*HH + h)*DH)*SS;
    const float* Vg0 = v + ((size_t)b*SS*HH + h)*DD;

    // Load Q tile (k-major) once
    for (int idx = tid; idx < 64*64; idx += 256) {
        int c = idx >> 6, r = idx & 63;
        QsT[idx] = Qg[(size_t)c*SS + r];
    }

    float mrow[4], lrow[4];
    #pragma unroll
    for (int rx = 0; rx < 4; rx++) { mrow[rx] = -INFINITY; lrow[rx] = 0.0f; }

    unsigned long long o2[4][4];
    #pragma unroll
    for (int rx = 0; rx < 4; rx++)
        #pragma unroll
        for (int c2 = 0; c2 < 4; c2++) o2[rx][c2] = 0ULL;

    for (int kt = 0; kt < SS/BN; ++kt) {
        __syncthreads();   // tiles free (prev GEMM2 done)

        // K' tile (k-major) + V tile (direct from original layout)
        const float* Kg = Kg0 + kt*BN;
        for (int idx = tid; idx < 64*64; idx += 256) {
            int c = idx >> 6, r = idx & 63;
            KsT[idx] = Kg[(size_t)c*SS + r];
        }
        {
            const float* Vg = Vg0 + (size_t)(kt*BN)*HH*DD;
            for (int idx = tid; idx < 64*32; idx += 256) {
                int r = idx >> 5, c4 = idx & 31;
                *(float4*)&Vs[r*DD + c4*4] =
                    *(const float4*)&Vg[(size_t)r*HH*DD + c4*4];
            }
        }
        __syncthreads();

        // ---- GEMM1: S = Q'K'^T, acc packed along n ----
        unsigned long long acc2[4][2];
        #pragma unroll
        for (int rx = 0; rx < 4; rx++) { acc2[rx][0] = 0ULL; acc2[rx][1] = 0ULL; }

        #pragma unroll 16
        for (int kk = 0; kk < DH; ++kk) {
            float4 a4 = *(const float4*)&QsT[(kk << 6) + (ti << 2)];
            ulonglong2 b2 = *(const ulonglong2*)&KsT[(kk << 6) + (tj << 2)];
            unsigned long long a0 = bcast2(a4.x), a1 = bcast2(a4.y);
            unsigned long long a2 = bcast2(a4.z), a3 = bcast2(a4.w);
            ffma2(acc2[0][0], a0, b2.x); ffma2(acc2[0][1], a0, b2.y);
            ffma2(acc2[1][0], a1, b2.x); ffma2(acc2[1][1], a1, b2.y);
            ffma2(acc2[2][0], a2, b2.x); ffma2(acc2[2][1], a2, b2.y);
            ffma2(acc2[3][0], a3, b2.x); ffma2(acc2[3][1], a3, b2.y);
        }

        // ---- register softmax with 16-lane shuffle reductions ----
        float p[4][4];
        #pragma unroll
        for (int rx = 0; rx < 4; rx++) {
            unpack2(acc2[rx][0], p[rx][0], p[rx][1]);
            unpack2(acc2[rx][1], p[rx][2], p[rx][3]);
        }
        const float sc = 1.0f / 64.0f;   // exact power of two (== 2/128)
        #pragma unroll
        for (int rx = 0; rx < 4; rx++) {
            float t = fmaxf(fmaxf(p[rx][0], p[rx][1]), fmaxf(p[rx][2], p[rx][3]));
            t = fmaxf(t, __shfl_xor_sync(0xffffffffu, t, 1));
            t = fmaxf(t, __shfl_xor_sync(0xffffffffu, t, 2));
            t = fmaxf(t, __shfl_xor_sync(0xffffffffu, t, 4));
            t = fmaxf(t, __shfl_xor_sync(0xffffffffu, t, 8));
            float mn = fmaxf(mrow[rx], t * sc);
            float f  = expf(mrow[rx] - mn);   // expf(-inf)=0 on first tile
            mrow[rx] = mn;
            float s0 = 0.0f;
            #pragma unroll
            for (int cx = 0; cx < 4; cx++) {
                p[rx][cx] = expf(fmaf(p[rx][cx], sc, -mn));
                s0 += p[rx][cx];
            }
            s0 += __shfl_xor_sync(0xffffffffu, s0, 1);
            s0 += __shfl_xor_sync(0xffffffffu, s0, 2);
            s0 += __shfl_xor_sync(0xffffffffu, s0, 4);
            s0 += __shfl_xor_sync(0xffffffffu, s0, 8);
            lrow[rx] = lrow[rx]*f + s0;

            int prow = (ti*4 + rx)*PSTR + tj*4;
            *(float2*)&Ps[prow]     = make_float2(p[rx][0], p[rx][1]);
            *(float2*)&Ps[prow + 2] = make_float2(p[rx][2], p[rx][3]);

            unsigned long long f2 = bcast2(f);
            #pragma unroll
            for (int c2 = 0; c2 < 4; c2++) o2[rx][c2] = mul2(o2[rx][c2], f2);
        }
        __syncwarp();   // Ps rows are warp-private: writer lanes == reader lanes' warp

        // ---- GEMM2: O += P V, o packed along d ----
        #pragma unroll 8
        for (int kk = 0; kk < BN; ++kk) {
            ulonglong2 v0 = *(const ulonglong2*)&Vs[kk*DD + tj*8];
            ulonglong2 v1 = *(const ulonglong2*)&Vs[kk*DD + tj*8 + 4];
            #pragma unroll
            for (int rx = 0; rx < 4; rx++) {
                unsigned long long a2 = bcast2(Ps[(ti*4 + rx)*PSTR + kk]);
                ffma2(o2[rx][0], a2, v0.x);
                ffma2(o2[rx][1], a2, v0.y);
                ffma2(o2[rx][2], a2, v1.x);
                ffma2(o2[rx][3], a2, v1.y);
            }
        }
    }

    // ---- normalize + write out[b,s,h,d] ----
    #pragma unroll
    for (int rx = 0; rx < 4; rx++) {
        int srow = qt*BM + ti*4 + rx;
        float inv_l = 1.0f / lrow[rx];
        float w[8];
        unpack2(o2[rx][0], w[0], w[1]); unpack2(o2[rx][1], w[2], w[3]);
        unpack2(o2[rx][2], w[4], w[5]); unpack2(o2[rx][3], w[6], w[7]);
        float* op = out + (((size_t)b*SS + srow)*HH + h)*DD + tj*8;
        float4 w0, w1;
        w0.x = w[0]*inv_l; w0.y = w[1]*inv_l; w0.z = w[2]*inv_l; w0.w = w[3]*inv_l;
        w1.x = w[4]*inv_l; w1.y = w[5]*inv_l; w1.z = w[6]*inv_l; w1.w = w[7]*inv_l;
        *(float4*)op = w0;
        *(float4*)(op + 4) = w1;
    }
}

extern "C" void kernel_launch(void* const* d_in, const int* in_sizes, int n_in,
                              void* d_out, int out_size) {
    const float* q = (const float*)d_in[0];
    const float* k = (const float*)d_in[1];
    const float* v = (const float*)d_in[2];
    float* out = (float*)d_out;

    const int smem = (4096 + 4096 + 8192 + BM*PSTR) * (int)sizeof(float);  // 82432 B
    cudaFuncSetAttribute(attn_kernel, cudaFuncAttributeMaxDynamicSharedMemorySize, smem);

    init_inv<<<1, 64>>>();
    dim3 pgrid(SS/64, HH, BB);
    prep_qk<<<pgrid, 256>>>(q, k);

    dim3 grid(SS/BM, HH, BB);
    attn_kernel<<<grid, 256, smem>>>(v, out);
}

// round 4
// speedup vs baseline: 1.3748x; 1.2004x over previous
#include <cuda_runtime.h>
#include <math.h>

#define BB 4
#define SS 2048
#define HH 16
#define DD 128
#define DH 64    // effective qk dim (first half, duplicated in reference)
#define BM 128
#define BN 64
#define PSTR 68

typedef unsigned long long u64;

// Scratch (no allocations allowed): k-major preprocessed Q', K'.
__device__ float g_Qp[BB*HH*DH*SS];   // [b,h,kdim,s]  33.5 MB
__device__ float g_Kp[BB*HH*DH*SS];   // [b,h,kdim,s]  33.5 MB
__device__ float g_inv[DH];

// ---------------- packed f32x2 helpers (sm_103a) ----------------
__device__ __forceinline__ u64 bcast2(float x) {
    u64 r;
    asm("mov.b64 %0, {%1, %1};" : "=l"(r) : "f"(x));
    return r;
}
__device__ __forceinline__ void ffma2(u64& d, u64 a, u64 b) {
    asm("fma.rn.f32x2 %0, %1, %2, %3;" : "=l"(d) : "l"(a), "l"(b), "l"(d));
}
__device__ __forceinline__ u64 mul2(u64 a, u64 b) {
    u64 d;
    asm("mul.rn.f32x2 %0, %1, %2;" : "=l"(d) : "l"(a), "l"(b));
    return d;
}
__device__ __forceinline__ void unpack2(u64 v, float& lo, float& hi) {
    asm("mov.b64 {%0, %1}, %2;" : "=f"(lo), "=f"(hi) : "l"(v));
}

// ---------------- prep ----------------
__global__ void init_inv() {
    int i = threadIdx.x;
    g_inv[i] = (float)exp(-(double)i * (9.210340371976184 / 64.0)); // ln(1e4)/64
}

// Tiled transpose: q,k [b,s,h,128] (first 64 dims) * fc -> [b,h,64,s]
__global__ void prep_qk(const float* __restrict__ q, const float* __restrict__ k) {
    __shared__ float qs[64*65];
    __shared__ float ks[64*65];
    const int st = blockIdx.x, h = blockIdx.y, b = blockIdx.z;
    const int tid = threadIdx.x;
    for (int idx = tid; idx < 64*64; idx += 256) {
        int sl = idx >> 6, i = idx & 63;
        int s = st*64 + sl;
        float fc = 2.0f * ((float)s * g_inv[i]);
        size_t gin = ((size_t)(b*SS + s)*HH + h)*DD + i;
        qs[i*65 + sl] = q[gin] * fc;
        ks[i*65 + sl] = k[gin] * fc;
    }
    __syncthreads();
    float* Qo = g_Qp + (size_t)((b*HH + h)*DH)*SS + st*64;
    float* Ko = g_Kp + (size_t)((b*HH + h)*DH)*SS + st*64;
    for (int idx = tid; idx < 64*64; idx += 256) {
        int i = idx >> 6, sl = idx & 63;
        Qo[(size_t)i*SS + sl] = qs[i*65 + sl];
        Ko[(size_t)i*SS + sl] = ks[i*65 + sl];
    }
}

// ---------------- flash attention, BM=128, FFMA2 micro-kernels ----------------
// 256 threads as 16x16: thread (ti,tj) owns rows ti*8..+7.
// GEMM1: cols tj*4..+3 (acc m-packed). GEMM2: d = {tj*4..+3, 64+tj*4..+3} (o d-packed).
__global__ __launch_bounds__(256, 1)
void attn_kernel(const float* __restrict__ v, float* __restrict__ out) {
    extern __shared__ float sm[];
    float* QsT = sm;                 // [64 kdim][128 m]
    float* KsT = QsT + DH*BM;        // [64 kdim][64 n]
    float* Vs  = KsT + DH*BN;        // [64 n][128 d]
    float* Ps  = Vs + BN*DD;         // [128 m][PSTR]

    const int qt = blockIdx.x, h = blockIdx.y, b = blockIdx.z;
    const int tid = threadIdx.x;
    const int ti = tid >> 4;         // 0..15
    const int tj = tid & 15;         // 0..15

    const float* Qg  = g_Qp + (size_t)((b*HH + h)*DH)*SS + qt*BM;
    const float* Kg0 = g_Kp + (size_t)((b*HH + h)*DH)*SS;
    const float* Vg0 = v + ((size_t)b*SS*HH + h)*DD;

    // Load Q tile (k-major) once: 64 rows of 128 contiguous floats
    for (int idx = tid; idx < DH*BM; idx += 256) {
        int kk = idx >> 7, m = idx & 127;
        QsT[idx] = Qg[(size_t)kk*SS + m];
    }

    float mrow[8], lrow[8];
    #pragma unroll
    for (int r = 0; r < 8; r++) { mrow[r] = -INFINITY; lrow[r] = 0.0f; }

    u64 o2[8][4];   // rows x 4 d-pairs (d: tj*4..+3, 64+tj*4..+3)
    #pragma unroll
    for (int r = 0; r < 8; r++)
        #pragma unroll
        for (int c = 0; c < 4; c++) o2[r][c] = 0ULL;

    for (int kt = 0; kt < SS/BN; ++kt) {
        __syncthreads();   // prev GEMM2 done with KsT/Vs

        const float* Kg = Kg0 + kt*BN;
        for (int idx = tid; idx < DH*BN; idx += 256) {
            int kk = idx >> 6, n = idx & 63;
            KsT[idx] = Kg[(size_t)kk*SS + n];
        }
        {
            const float* Vg = Vg0 + (size_t)(kt*BN)*HH*DD;
            for (int idx = tid; idx < BN*DD/4; idx += 256) {
                int r = idx >> 5, c4 = idx & 31;
                *(float4*)&Vs[r*DD + c4*4] =
                    *(const float4*)&Vg[(size_t)r*HH*DD + c4*4];
            }
        }
        __syncthreads();

        // ---- GEMM1: S = Q'K'^T. acc m-packed: acc2[mp][n] = rows {2mp,2mp+1} ----
        u64 acc2[4][4];
        #pragma unroll
        for (int mp = 0; mp < 4; mp++)
            #pragma unroll
            for (int n = 0; n < 4; n++) acc2[mp][n] = 0ULL;

        #pragma unroll 16
        for (int kk = 0; kk < DH; ++kk) {
            // a: 8 consecutive m floats = 4 packed row-pairs, loaded directly
            ulonglong2 a01 = *(const ulonglong2*)&QsT[(kk << 7) + (ti << 3)];
            ulonglong2 a23 = *(const ulonglong2*)&QsT[(kk << 7) + (ti << 3) + 4];
            float4 b4 = *(const float4*)&KsT[(kk << 6) + (tj << 2)];
            u64 b0 = bcast2(b4.x), b1 = bcast2(b4.y);
            u64 b2 = bcast2(b4.z), b3 = bcast2(b4.w);
            ffma2(acc2[0][0], a01.x, b0); ffma2(acc2[0][1], a01.x, b1);
            ffma2(acc2[0][2], a01.x, b2); ffma2(acc2[0][3], a01.x, b3);
            ffma2(acc2[1][0], a01.y, b0); ffma2(acc2[1][1], a01.y, b1);
            ffma2(acc2[1][2], a01.y, b2); ffma2(acc2[1][3], a01.y, b3);
            ffma2(acc2[2][0], a23.x, b0); ffma2(acc2[2][1], a23.x, b1);
            ffma2(acc2[2][2], a23.x, b2); ffma2(acc2[2][3], a23.x, b3);
            ffma2(acc2[3][0], a23.y, b0); ffma2(acc2[3][1], a23.y, b1);
            ffma2(acc2[3][2], a23.y, b2); ffma2(acc2[3][3], a23.y, b3);
        }

        // ---- register softmax, 16-lane shuffle reductions ----
        float p[8][4];
        #pragma unroll
        for (int mp = 0; mp < 4; mp++)
            #pragma unroll
            for (int n = 0; n < 4; n++)
                unpack2(acc2[mp][n], p[2*mp][n], p[2*mp + 1][n]);

        const float sc = 1.0f / 64.0f;   // exact power of two (== 2/128)
        #pragma unroll
        for (int r = 0; r < 8; r++) {
            float t = fmaxf(fmaxf(p[r][0], p[r][1]), fmaxf(p[r][2], p[r][3]));
            t = fmaxf(t, __shfl_xor_sync(0xffffffffu, t, 1));
            t = fmaxf(t, __shfl_xor_sync(0xffffffffu, t, 2));
            t = fmaxf(t, __shfl_xor_sync(0xffffffffu, t, 4));
            t = fmaxf(t, __shfl_xor_sync(0xffffffffu, t, 8));
            float mn = fmaxf(mrow[r], t * sc);
            float f  = expf(mrow[r] - mn);   // expf(-inf)=0 on first tile
            mrow[r] = mn;
            float s0 = 0.0f;
            #pragma unroll
            for (int cx = 0; cx < 4; cx++) {
                p[r][cx] = expf(fmaf(p[r][cx], sc, -mn));
                s0 += p[r][cx];
            }
            s0 += __shfl_xor_sync(0xffffffffu, s0, 1);
            s0 += __shfl_xor_sync(0xffffffffu, s0, 2);
            s0 += __shfl_xor_sync(0xffffffffu, s0, 4);
            s0 += __shfl_xor_sync(0xffffffffu, s0, 8);
            lrow[r] = lrow[r]*f + s0;

            float4 pw; pw.x = p[r][0]; pw.y = p[r][1]; pw.z = p[r][2]; pw.w = p[r][3];
            *(float4*)&Ps[(ti*8 + r)*PSTR + tj*4] = pw;

            u64 f2 = bcast2(f);
            #pragma unroll
            for (int c = 0; c < 4; c++) o2[r][c] = mul2(o2[r][c], f2);
        }
        __syncwarp();   // Ps rows ti*8+r written/read by the same 16-lane groups

        // ---- GEMM2: O += P V, o d-packed; Ps via float4 fragments ----
        #pragma unroll 2
        for (int kc = 0; kc < BN/4; ++kc) {
            float4 pr[8];
            #pragma unroll
            for (int r = 0; r < 8; r++)
                pr[r] = *(const float4*)&Ps[(ti*8 + r)*PSTR + kc*4];
            #pragma unroll
            for (int j = 0; j < 4; j++) {
                int kk = kc*4 + j;
                ulonglong2 v0 = *(const ulonglong2*)&Vs[kk*DD + tj*4];
                ulonglong2 v1 = *(const ulonglong2*)&Vs[kk*DD + 64 + tj*4];
                #pragma unroll
                for (int r = 0; r < 8; r++) {
                    float pv = (j == 0) ? pr[r].x : (j == 1) ? pr[r].y
                             : (j == 2) ? pr[r].z : pr[r].w;
                    u64 a2 = bcast2(pv);
                    ffma2(o2[r][0], a2, v0.x);
                    ffma2(o2[r][1], a2, v0.y);
                    ffma2(o2[r][2], a2, v1.x);
                    ffma2(o2[r][3], a2, v1.y);
                }
            }
        }
    }

    // ---- normalize + write out[b,s,h,d]; d = tj*4 and 64+tj*4 ----
    #pragma unroll
    for (int r = 0; r < 8; r++) {
        int srow = qt*BM + ti*8 + r;
        float inv_l = 1.0f / lrow[r];
        float w[8];
        unpack2(o2[r][0], w[0], w[1]); unpack2(o2[r][1], w[2], w[3]);
        unpack2(o2[r][2], w[4], w[5]); unpack2(o2[r][3], w[6], w[7]);
        float* op = out + (((size_t)b*SS + srow)*HH + h)*DD;
        float4 w0, w1;
        w0.x = w[0]*inv_l; w0.y = w[1]*inv_l; w0.z = w[2]*inv_l; w0.w = w[3]*inv_l;
        w1.x = w[4]*inv_l; w1.y = w[5]*inv_l; w1.z = w[6]*inv_l; w1.w = w[7]*inv_l;
        *(float4*)(op + tj*4)      = w0;
        *(float4*)(op + 64 + tj*4) = w1;
    }
}

extern "C" void kernel_launch(void* const* d_in, const int* in_sizes, int n_in,
                              void* d_out, int out_size) {
    const float* q = (const float*)d_in[0];
    const float* k = (const float*)d_in[1];
    const float* v = (const float*)d_in[2];
    float* out = (float*)d_out;

    const int smem = (DH*BM + DH*BN + BN*DD + BM*PSTR) * (int)sizeof(float); // 116736 B
    cudaFuncSetAttribute(attn_kernel, cudaFuncAttributeMaxDynamicSharedMemorySize, smem);

    init_inv<<<1, 64>>>();
    dim3 pgrid(SS/64, HH, BB);
    prep_qk<<<pgrid, 256>>>(q, k);

    dim3 grid(SS/BM, HH, BB);
    attn_kernel<<<grid, 256, smem>>>(v, out);
}

// round 5
// speedup vs baseline: 1.9179x; 1.3950x over previous
#include <cuda_runtime.h>
#include <math.h>
#include <stdint.h>

#define BB 4
#define SS 2048
#define HH 16
#define DD 128
#define DH 64    // effective qk dim (first half, duplicated in reference)
#define BM 128
#define BN 64
#define PSTR 68

typedef unsigned long long u64;

// Scratch (no allocations allowed): k-major preprocessed Q', K'.
__device__ float g_Qp[BB*HH*DH*SS];   // [b,h,kdim,s]  33.5 MB
__device__ float g_Kp[BB*HH*DH*SS];   // [b,h,kdim,s]  33.5 MB
__device__ float g_inv[DH];

// ---------------- packed f32x2 helpers (sm_103a) ----------------
__device__ __forceinline__ u64 bcast2(float x) {
    u64 r;
    asm("mov.b64 %0, {%1, %1};" : "=l"(r) : "f"(x));
    return r;
}
__device__ __forceinline__ void ffma2(u64& d, u64 a, u64 b) {
    asm("fma.rn.f32x2 %0, %1, %2, %3;" : "=l"(d) : "l"(a), "l"(b), "l"(d));
}
__device__ __forceinline__ u64 mul2(u64 a, u64 b) {
    u64 d;
    asm("mul.rn.f32x2 %0, %1, %2;" : "=l"(d) : "l"(a), "l"(b));
    return d;
}
__device__ __forceinline__ void unpack2(u64 v, float& lo, float& hi) {
    asm("mov.b64 {%0, %1}, %2;" : "=f"(lo), "=f"(hi) : "l"(v));
}

// ---------------- cp.async helpers ----------------
__device__ __forceinline__ void cp_async16(uint32_t saddr, const void* gptr) {
    asm volatile("cp.async.cg.shared.global [%0], [%1], 16;"
                 :: "r"(saddr), "l"(gptr));
}
__device__ __forceinline__ void cp_commit() {
    asm volatile("cp.async.commit_group;");
}
__device__ __forceinline__ void cp_wait_all() {
    asm volatile("cp.async.wait_group 0;");
}

// ---------------- prep ----------------
__global__ void init_inv() {
    int i = threadIdx.x;
    g_inv[i] = (float)exp(-(double)i * (9.210340371976184 / 64.0)); // ln(1e4)/64
}

// Tiled transpose: q,k [b,s,h,128] (first 64 dims) * fc -> [b,h,64,s]
__global__ void prep_qk(const float* __restrict__ q, const float* __restrict__ k) {
    __shared__ float qs[64*65];
    __shared__ float ks[64*65];
    const int st = blockIdx.x, h = blockIdx.y, b = blockIdx.z;
    const int tid = threadIdx.x;
    for (int idx = tid; idx < 64*64; idx += 256) {
        int sl = idx >> 6, i = idx & 63;
        int s = st*64 + sl;
        float fc = 2.0f * ((float)s * g_inv[i]);
        size_t gin = ((size_t)(b*SS + s)*HH + h)*DD + i;
        qs[i*65 + sl] = q[gin] * fc;
        ks[i*65 + sl] = k[gin] * fc;
    }
    __syncthreads();
    float* Qo = g_Qp + (size_t)((b*HH + h)*DH)*SS + st*64;
    float* Ko = g_Kp + (size_t)((b*HH + h)*DH)*SS + st*64;
    for (int idx = tid; idx < 64*64; idx += 256) {
        int i = idx >> 6, sl = idx & 63;
        Qo[(size_t)i*SS + sl] = qs[i*65 + sl];
        Ko[(size_t)i*SS + sl] = ks[i*65 + sl];
    }
}

// ---------------- flash attention: BM=128, FFMA2, cp.async double buffer ----
// 256 threads as 16x16: thread (ti,tj) owns rows ti*8..+7.
// GEMM1: cols tj*4..+3 (acc m-packed). GEMM2: d = {tj*4..+3, 64+tj*4..+3}.
__global__ __launch_bounds__(256, 1)
void attn_kernel(const float* __restrict__ v, float* __restrict__ out) {
    extern __shared__ float sm[];
    float* QsT = sm;                          // [64][128]              8192
    float* Ks0 = QsT + DH*BM;                 // 2 x [64][64]           8192
    float* Vs0 = Ks0 + 2*DH*BN;               // 2 x [64][128]         16384
    float* Ps  = Vs0 + 2*BN*DD;               // [128][PSTR]            8704

    const int qt = blockIdx.x, h = blockIdx.y, b = blockIdx.z;
    const int tid = threadIdx.x;
    const int ti = tid >> 4;         // 0..15
    const int tj = tid & 15;         // 0..15

    const float* Qg  = g_Qp + (size_t)((b*HH + h)*DH)*SS + qt*BM;
    const float* Kg0 = g_Kp + (size_t)((b*HH + h)*DH)*SS;
    const float* Vg0 = v + ((size_t)b*SS*HH + h)*DD;

    const uint32_t s_qst = (uint32_t)__cvta_generic_to_shared(QsT);
    const uint32_t s_ks  = (uint32_t)__cvta_generic_to_shared(Ks0);
    const uint32_t s_vs  = (uint32_t)__cvta_generic_to_shared(Vs0);

    // ---- prologue: Q tile + tile 0 of K/V via cp.async ----
    // Q: 2048 float4, 8 per thread
    #pragma unroll
    for (int it = 0; it < 8; it++) {
        int idx4 = tid + it*256;
        int kk = idx4 >> 5, m4 = idx4 & 31;
        cp_async16(s_qst + (uint32_t)idx4*16, Qg + (size_t)kk*SS + m4*4);
    }
    // K tile 0: 1024 float4, 4 per thread
    #pragma unroll
    for (int it = 0; it < 4; it++) {
        int idx4 = tid + it*256;
        int kk = idx4 >> 4, n4 = idx4 & 15;
        cp_async16(s_ks + (uint32_t)idx4*16, Kg0 + (size_t)kk*SS + n4*4);
    }
    // V tile 0: 2048 float4, 8 per thread
    #pragma unroll
    for (int it = 0; it < 8; it++) {
        int idx4 = tid + it*256;
        int r = idx4 >> 5, c4 = idx4 & 31;
        cp_async16(s_vs + (uint32_t)idx4*16, Vg0 + (size_t)r*HH*DD + c4*4);
    }
    cp_commit();

    float mrow[8], lrow[8];   // mrow in base-2 (log2) units
    #pragma unroll
    for (int r = 0; r < 8; r++) { mrow[r] = -INFINITY; lrow[r] = 0.0f; }

    u64 o2[8][4];
    #pragma unroll
    for (int r = 0; r < 8; r++)
        #pragma unroll
        for (int c = 0; c < 4; c++) o2[r][c] = 0ULL;

    int buf = 0;
    for (int kt = 0; kt < SS/BN; ++kt) {
        cp_wait_all();
        __syncthreads();   // tile[buf] ready; prev compute done with tile[buf^1]

        // issue next tile into buf^1 (overlaps with this iteration's compute)
        if (kt + 1 < SS/BN) {
            const float* Kg = Kg0 + (kt + 1)*BN;
            const float* Vg = Vg0 + (size_t)((kt + 1)*BN)*HH*DD;
            uint32_t ks_dst = s_ks + (uint32_t)(buf ^ 1)*DH*BN*4;
            uint32_t vs_dst = s_vs + (uint32_t)(buf ^ 1)*BN*DD*4;
            #pragma unroll
            for (int it = 0; it < 4; it++) {
                int idx4 = tid + it*256;
                int kk = idx4 >> 4, n4 = idx4 & 15;
                cp_async16(ks_dst + (uint32_t)idx4*16, Kg + (size_t)kk*SS + n4*4);
            }
            #pragma unroll
            for (int it = 0; it < 8; it++) {
                int idx4 = tid + it*256;
                int r = idx4 >> 5, c4 = idx4 & 31;
                cp_async16(vs_dst + (uint32_t)idx4*16, Vg + (size_t)r*HH*DD + c4*4);
            }
        }
        cp_commit();   // empty group when no issue: wait_group 0 still fine

        const float* KsT = Ks0 + buf*DH*BN;
        const float* Vs  = Vs0 + buf*BN*DD;

        // ---- GEMM1: S = Q'K'^T. acc m-packed: acc2[mp][n] = rows {2mp,2mp+1} ----
        u64 acc2[4][4];
        #pragma unroll
        for (int mp = 0; mp < 4; mp++)
            #pragma unroll
            for (int n = 0; n < 4; n++) acc2[mp][n] = 0ULL;

        #pragma unroll 16
        for (int kk = 0; kk < DH; ++kk) {
            ulonglong2 a01 = *(const ulonglong2*)&QsT[(kk << 7) + (ti << 3)];
            ulonglong2 a23 = *(const ulonglong2*)&QsT[(kk << 7) + (ti << 3) + 4];
            float4 b4 = *(const float4*)&KsT[(kk << 6) + (tj << 2)];
            u64 b0 = bcast2(b4.x), b1 = bcast2(b4.y);
            u64 b2 = bcast2(b4.z), b3 = bcast2(b4.w);
            ffma2(acc2[0][0], a01.x, b0); ffma2(acc2[0][1], a01.x, b1);
            ffma2(acc2[0][2], a01.x, b2); ffma2(acc2[0][3], a01.x, b3);
            ffma2(acc2[1][0], a01.y, b0); ffma2(acc2[1][1], a01.y, b1);
            ffma2(acc2[1][2], a01.y, b2); ffma2(acc2[1][3], a01.y, b3);
            ffma2(acc2[2][0], a23.x, b0); ffma2(acc2[2][1], a23.x, b1);
            ffma2(acc2[2][2], a23.x, b2); ffma2(acc2[2][3], a23.x, b3);
            ffma2(acc2[3][0], a23.y, b0); ffma2(acc2[3][1], a23.y, b1);
            ffma2(acc2[3][2], a23.y, b2); ffma2(acc2[3][3], a23.y, b3);
        }

        // ---- softmax in base-2: logit2 = acc * (log2e/64) ----
        float p[8][4];
        #pragma unroll
        for (int mp = 0; mp < 4; mp++)
            #pragma unroll
            for (int n = 0; n < 4; n++)
                unpack2(acc2[mp][n], p[2*mp][n], p[2*mp + 1][n]);

        const float sc2 = 1.44269504088896340736f / 64.0f;  // log2(e)/64

        float mx[8];
        #pragma unroll
        for (int r = 0; r < 8; r++)
            mx[r] = fmaxf(fmaxf(p[r][0], p[r][1]), fmaxf(p[r][2], p[r][3]));
        #pragma unroll
        for (int st = 1; st < 16; st <<= 1)
            #pragma unroll
            for (int r = 0; r < 8; r++)
                mx[r] = fmaxf(mx[r], __shfl_xor_sync(0xffffffffu, mx[r], st));

        float fr[8];
        #pragma unroll
        for (int r = 0; r < 8; r++) {
            float mn = fmaxf(mrow[r], mx[r]*sc2);
            fr[r] = exp2f(mrow[r] - mn);   // exp2f(-inf)=0 on first tile
            mrow[r] = mn;
        }

        float sr[8];
        #pragma unroll
        for (int r = 0; r < 8; r++) {
            #pragma unroll
            for (int cx = 0; cx < 4; cx++)
                p[r][cx] = exp2f(fmaf(p[r][cx], sc2, -mrow[r]));
            sr[r] = (p[r][0] + p[r][1]) + (p[r][2] + p[r][3]);
            float4 pw; pw.x = p[r][0]; pw.y = p[r][1]; pw.z = p[r][2]; pw.w = p[r][3];
            *(float4*)&Ps[(ti*8 + r)*PSTR + tj*4] = pw;
        }
        #pragma unroll
        for (int st = 1; st < 16; st <<= 1)
            #pragma unroll
            for (int r = 0; r < 8; r++)
                sr[r] += __shfl_xor_sync(0xffffffffu, sr[r], st);
        #pragma unroll
        for (int r = 0; r < 8; r++) {
            lrow[r] = lrow[r]*fr[r] + sr[r];
            u64 f2 = bcast2(fr[r]);
            #pragma unroll
            for (int c = 0; c < 4; c++) o2[r][c] = mul2(o2[r][c], f2);
        }
        __syncwarp();   // Ps rows ti*8+r written/read by the same 16-lane groups

        // ---- GEMM2: O += P V ----
        #pragma unroll 2
        for (int kc = 0; kc < BN/4; ++kc) {
            float4 pr[8];
            #pragma unroll
            for (int r = 0; r < 8; r++)
                pr[r] = *(const float4*)&Ps[(ti*8 + r)*PSTR + kc*4];
            #pragma unroll
            for (int j = 0; j < 4; j++) {
                int kk = kc*4 + j;
                ulonglong2 v0 = *(const ulonglong2*)&Vs[kk*DD + tj*4];
                ulonglong2 v1 = *(const ulonglong2*)&Vs[kk*DD + 64 + tj*4];
                #pragma unroll
                for (int r = 0; r < 8; r++) {
                    float pv = (j == 0) ? pr[r].x : (j == 1) ? pr[r].y
                             : (j == 2) ? pr[r].z : pr[r].w;
                    u64 a2 = bcast2(pv);
                    ffma2(o2[r][0], a2, v0.x);
                    ffma2(o2[r][1], a2, v0.y);
                    ffma2(o2[r][2], a2, v1.x);
                    ffma2(o2[r][3], a2, v1.y);
                }
            }
        }
        buf ^= 1;
    }

    // ---- normalize + write out[b,s,h,d]; d = tj*4 and 64+tj*4 ----
    #pragma unroll
    for (int r = 0; r < 8; r++) {
        int srow = qt*BM + ti*8 + r;
        float inv_l = 1.0f / lrow[r];
        float w[8];
        unpack2(o2[r][0], w[0], w[1]); unpack2(o2[r][1], w[2], w[3]);
        unpack2(o2[r][2], w[4], w[5]); unpack2(o2[r][3], w[6], w[7]);
        float* op = out + (((size_t)b*SS + srow)*HH + h)*DD;
        float4 w0, w1;
        w0.x = w[0]*inv_l; w0.y = w[1]*inv_l; w0.z = w[2]*inv_l; w0.w = w[3]*inv_l;
        w1.x = w[4]*inv_l; w1.y = w[5]*inv_l; w1.z = w[6]*inv_l; w1.w = w[7]*inv_l;
        *(float4*)(op + tj*4)      = w0;
        *(float4*)(op + 64 + tj*4) = w1;
    }
}

extern "C" void kernel_launch(void* const* d_in, const int* in_sizes, int n_in,
                              void* d_out, int out_size) {
    const float* q = (const float*)d_in[0];
    const float* k = (const float*)d_in[1];
    const float* v = (const float*)d_in[2];
    float* out = (float*)d_out;

    const int smem = (DH*BM + 2*DH*BN + 2*BN*DD + BM*PSTR) * (int)sizeof(float); // 165888 B
    cudaFuncSetAttribute(attn_kernel, cudaFuncAttributeMaxDynamicSharedMemorySize, smem);

    init_inv<<<1, 64>>>();
    dim3 pgrid(SS/64, HH, BB);
    prep_qk<<<pgrid, 256>>>(q, k);

    dim3 grid(SS/BM, HH, BB);
    attn_kernel<<<grid, 256, smem>>>(v, out);
}